// round 2
// baseline (speedup 1.0000x reference)
#include <cuda_runtime.h>

typedef unsigned long long ull;

#define B_TOK 32768
#define H_DIM 4096
#define G_NUM 16
#define EPG_N 16
#define E_NUM 256

#define TOK  128    // tokens per CTA tile
#define KC   64     // K chunk
#define ASTR 68     // KC + 4 pad (bank-conflict mitigation)
#define NTHR 256

// scratch (no allocations allowed)
__device__ int g_cnt[G_NUM];
__device__ int g_bucket[G_NUM * B_TOK];

__device__ __forceinline__ void ffma2(ull& acc, ull a, ull w) {
    // packed f32x2 FMA (FFMA2) — 2 fp32 MACs per instruction
    asm volatile("fma.rn.f32x2 %0, %1, %2, %0;" : "+l"(acc) : "l"(a), "l"(w));
}

__device__ __forceinline__ float fsum2(ull v) {
    union { ull u; float2 f; } t; t.u = v;
    return t.f.x + t.f.y;
}

__global__ void zero_cnt_kernel() {
    if (threadIdx.x < G_NUM) g_cnt[threadIdx.x] = 0;
}

// ---------------------------------------------------------------------------
// Phase 1: group logits GEMV [TOK x 16], argmax, bucket tokens by group.
// Thread blocking: 4 tokens x 2 outputs per thread (256 threads, 128x16 tile).
// ---------------------------------------------------------------------------
__global__ void __launch_bounds__(NTHR, 2) group_route_kernel(
    const float* __restrict__ hs, const float* __restrict__ gw)
{
    __shared__ float sA[TOK][ASTR];
    __shared__ float sW[G_NUM][ASTR];
    __shared__ int scnt[G_NUM];
    __shared__ int sbase[G_NUM];

    const int tid = threadIdx.x;
    const int b0  = blockIdx.x * TOK;
    const int tx  = tid & 7;          // output pair {2tx, 2tx+1}
    const int ty  = tid >> 3;         // token quad base 4*ty
    const int c4  = (tid & 15) * 4;   // loader column (floats)
    const int rg  = tid >> 4;         // loader row group

    ull acc[4][2];
#pragma unroll
    for (int t = 0; t < 4; t++) { acc[t][0] = 0ULL; acc[t][1] = 0ULL; }

    for (int k0 = 0; k0 < H_DIM; k0 += KC) {
        __syncthreads();
#pragma unroll
        for (int i = 0; i < 8; i++) {
            int row = rg + i * 16;
            *(float4*)&sA[row][c4] =
                *(const float4*)&hs[(size_t)(b0 + row) * H_DIM + k0 + c4];
        }
        *(float4*)&sW[rg][c4] = *(const float4*)&gw[(size_t)rg * H_DIM + k0 + c4];
        __syncthreads();

#pragma unroll
        for (int kk = 0; kk < KC; kk += 4) {
            ulonglong2 w0 = *(const ulonglong2*)&sW[2 * tx + 0][kk];
            ulonglong2 w1 = *(const ulonglong2*)&sW[2 * tx + 1][kk];
#pragma unroll
            for (int t = 0; t < 4; t++) {
                ulonglong2 a = *(const ulonglong2*)&sA[4 * ty + t][kk];
                ffma2(acc[t][0], a.x, w0.x);
                ffma2(acc[t][0], a.y, w0.y);
                ffma2(acc[t][1], a.x, w1.x);
                ffma2(acc[t][1], a.y, w1.y);
            }
        }
    }

    __syncthreads();
    float (*sC)[17] = reinterpret_cast<float(*)[17]>(&sA[0][0]);
#pragma unroll
    for (int t = 0; t < 4; t++) {
        sC[4 * ty + t][2 * tx + 0] = fsum2(acc[t][0]);
        sC[4 * ty + t][2 * tx + 1] = fsum2(acc[t][1]);
    }
    if (tid < G_NUM) scnt[tid] = 0;
    __syncthreads();

    int bg = 0, loff = 0;
    if (tid < TOK) {
        float best = sC[tid][0];
#pragma unroll
        for (int g = 1; g < G_NUM; g++) {
            float v = sC[tid][g];
            if (v > best) { best = v; bg = g; }   // first-index-wins like jnp.argmax
        }
        loff = atomicAdd(&scnt[bg], 1);
    }
    __syncthreads();
    if (tid < G_NUM) sbase[tid] = atomicAdd(&g_cnt[tid], scnt[tid]);
    __syncthreads();
    if (tid < TOK) g_bucket[bg * B_TOK + sbase[bg] + loff] = b0 + tid;
}

// ---------------------------------------------------------------------------
// Phase 2: per-group expert GEMM over bucketed tokens + softmax/argmax epilogue
// + full [B,E] output row write (zeros outside selected block).
// ---------------------------------------------------------------------------
__global__ void __launch_bounds__(NTHR, 2) expert_route_kernel(
    const float* __restrict__ hs, const float* __restrict__ ew,
    float* __restrict__ out)
{
    __shared__ float sA[TOK][ASTR];
    __shared__ float sW[EPG_N][ASTR];
    __shared__ int stok[TOK];

    const int tid = threadIdx.x;
    const int g   = blockIdx.x;
    const int cnt = g_cnt[g];
    const float* wg = ew + (size_t)g * EPG_N * H_DIM;

    const int tx = tid & 7;
    const int ty = tid >> 3;
    const int c4 = (tid & 15) * 4;
    const int rg = tid >> 4;

    const size_t OUT_SEL = (size_t)B_TOK * E_NUM;
    const size_t OUT_WGT = OUT_SEL + B_TOK;

    for (int tile = blockIdx.y; tile * TOK < cnt; tile += gridDim.y) {
        __syncthreads();
        if (tid < TOK) {
            int idx = tile * TOK + tid;
            stok[tid] = (idx < cnt) ? g_bucket[g * B_TOK + idx] : -1;
        }
        __syncthreads();

        ull acc[4][2];
#pragma unroll
        for (int t = 0; t < 4; t++) { acc[t][0] = 0ULL; acc[t][1] = 0ULL; }

        for (int k0 = 0; k0 < H_DIM; k0 += KC) {
            if (k0) __syncthreads();
#pragma unroll
            for (int i = 0; i < 8; i++) {
                int row = rg + i * 16;
                int tok = stok[row];
                if (tok >= 0)
                    *(float4*)&sA[row][c4] =
                        *(const float4*)&hs[(size_t)tok * H_DIM + k0 + c4];
            }
            *(float4*)&sW[rg][c4] = *(const float4*)&wg[(size_t)rg * H_DIM + k0 + c4];
            __syncthreads();

#pragma unroll
            for (int kk = 0; kk < KC; kk += 4) {
                ulonglong2 w0 = *(const ulonglong2*)&sW[2 * tx + 0][kk];
                ulonglong2 w1 = *(const ulonglong2*)&sW[2 * tx + 1][kk];
#pragma unroll
                for (int t = 0; t < 4; t++) {
                    ulonglong2 a = *(const ulonglong2*)&sA[4 * ty + t][kk];
                    ffma2(acc[t][0], a.x, w0.x);
                    ffma2(acc[t][0], a.y, w0.y);
                    ffma2(acc[t][1], a.x, w1.x);
                    ffma2(acc[t][1], a.y, w1.y);
                }
            }
        }

        __syncthreads();
        float (*sC)[17] = reinterpret_cast<float(*)[17]>(&sA[0][0]);
#pragma unroll
        for (int t = 0; t < 4; t++) {
            sC[4 * ty + t][2 * tx + 0] = fsum2(acc[t][0]);
            sC[4 * ty + t][2 * tx + 1] = fsum2(acc[t][1]);
        }
        __syncthreads();

        // per-token epilogue: softmax over 16 experts, argmax, weight
        if (tid < TOK && stok[tid] >= 0) {
            int token = stok[tid];
            float m = sC[tid][0];
            int bi = 0;
#pragma unroll
            for (int e = 1; e < EPG_N; e++) {
                float v = sC[tid][e];
                if (v > m) { m = v; bi = e; }
            }
            float s = 0.0f;
#pragma unroll
            for (int e = 0; e < EPG_N; e++) s += expf(sC[tid][e] - m);
            out[OUT_SEL + token] = (float)(g * EPG_N + bi);
            out[OUT_WGT + token] = 1.0f / s;   // exp(max-max)/sum
        }

        // cooperative all_expert_logits row write: 64 threads per token row,
        // 4 token rows per iteration, coalesced 1KB stores per row.
        const int slot_off = tid >> 6;   // 0..3
        const int cc4 = tid & 63;        // float4 column index in [0,64)
        for (int tb = 0; tb < TOK; tb += 4) {
            int slot = tb + slot_off;
            int token = stok[slot];
            if (token >= 0) {
                float4 v = make_float4(0.f, 0.f, 0.f, 0.f);
                if ((cc4 >> 2) == g) {
                    int lo = (cc4 & 3) * 4;
                    v = make_float4(sC[slot][lo], sC[slot][lo + 1],
                                    sC[slot][lo + 2], sC[slot][lo + 3]);
                }
                *(float4*)&out[(size_t)token * E_NUM + cc4 * 4] = v;
            }
        }
    }
}

extern "C" void kernel_launch(void* const* d_in, const int* in_sizes, int n_in,
                              void* d_out, int out_size) {
    const float* hs = (const float*)d_in[0];   // [32768, 4096]
    const float* gw = (const float*)d_in[1];   // [16, 4096]
    const float* ew = (const float*)d_in[2];   // [16, 16, 4096]
    float* out = (float*)d_out;                // [B*E] logits | [B] sel | [B] wgt

    zero_cnt_kernel<<<1, 32>>>();
    group_route_kernel<<<B_TOK / TOK, NTHR>>>(hs, gw);
    dim3 grid2(G_NUM, 24);
    expert_route_kernel<<<grid2, NTHR>>>(hs, ew, out);
}

// round 4
// speedup vs baseline: 1.3066x; 1.3066x over previous
#include <cuda_runtime.h>
#include <math.h>

typedef unsigned int u32;

#define BT 32768
#define HD 4096
#define GN 16
#define EPG 16
#define EN 256
#define NC 288              // padded output cols: 0-255 experts, 256-271 groups, 272-287 zero
#define KCH 32              // fp32 per K chunk
#define NCHUNK 128
#define TPB 512

#define AP 36               // A row pad (words) -> conflict-free frag LDS.32
#define LP 76               // per-lane W block (72 data + 4 pad) -> conflict-free LDS.128
#define A_BYTES (128 * AP * 4)          // 18432
#define W_BYTES (4 * 32 * LP * 4)       // 38912
#define BUF_BYTES (A_BYTES + W_BYTES)   // 57344
#define SCSTR 292
#define SMEM_TOTAL (1024 + 128 * SCSTR * 4)   // 150528 (pipeline needs 1024+2*57344)

#define THR 4e-3f

__device__ __align__(16) float g_wsw[(size_t)NCHUNK * 4 * 32 * LP];
__device__ int g_nfix;
__device__ int g_fix[BT];

// ---------------- primitives (all sm_80-era, safe on generic target) ----------
__device__ __forceinline__ void cpa16(u32 dst, const void* src) {
    asm volatile("cp.async.cg.shared.global [%0], [%1], 16;\n" :: "r"(dst), "l"(src));
}
#define CP_COMMIT() asm volatile("cp.async.commit_group;\n" ::: "memory")
#define CP_WAIT1()  asm volatile("cp.async.wait_group 1;\n" ::: "memory")
#define CP_WAIT0()  asm volatile("cp.async.wait_group 0;\n" ::: "memory")

__device__ __forceinline__ void mma8(float* c, const u32* a, u32 b0, u32 b1) {
    asm volatile(
        "mma.sync.aligned.m16n8k8.row.col.f32.tf32.tf32.f32 "
        "{%0,%1,%2,%3}, {%4,%5,%6,%7}, {%8,%9}, {%0,%1,%2,%3};"
        : "+f"(c[0]), "+f"(c[1]), "+f"(c[2]), "+f"(c[3])
        : "r"(a[0]), "r"(a[1]), "r"(a[2]), "r"(a[3]), "r"(b0), "r"(b1));
}

__device__ __forceinline__ u32 tf32rn(float v) {
    u32 r;
    asm("cvt.rna.tf32.f32 %0, %1;" : "=r"(r) : "f"(v));
    return r;
}

// ---------------- prep: W -> fragment-order image (one float4 per thread) ------
// layout: g_wsw[((chunk*4 + cg)*32 + lane)*LP + khalf*36 + t*4 + q]
//   value = W[col][k], col = cg*72 + t*8 + lane>>2,
//   k = chunk*32 + (khalf*2 + (q>>1))*8 + (lane&3) + (q&1)*4
__global__ void prep_kernel(const float* __restrict__ gw, const float* __restrict__ ew) {
    u32 u = blockIdx.x * 256 + threadIdx.x;     // 311296 quads total
    if (u == 0) g_nfix = 0;
    u32 i4 = u % (LP / 4);                       // 0..18
    u32 t2 = u / (LP / 4);
    u32 lane = t2 & 31;
    u32 cg = (t2 >> 5) & 3;
    u32 chunk = t2 >> 7;

    float4 v = make_float4(0.f, 0.f, 0.f, 0.f);
    u32* vp = (u32*)&v;
    if (i4 < 18) {                               // data quads (words 0..71)
        u32 i0 = i4 * 4;
        u32 khalf = i0 / 36;
        u32 j = i0 % 36;
        u32 t = j / 4;
        int col = cg * 72 + t * 8 + (lane >> 2);
#pragma unroll
        for (int q = 0; q < 4; q++) {
            int kk = khalf * 2 + (q >> 1);
            int k = chunk * KCH + kk * 8 + (lane & 3) + (q & 1) * 4;
            float w = 0.f;
            if (col < 256)      w = ew[(size_t)col * HD + k];
            else if (col < 272) w = gw[(size_t)(col - 256) * HD + k];
            vp[q] = tf32rn(w);
        }
    }
    *(float4*)&g_wsw[((size_t)(chunk * 4 + cg) * 32 + lane) * LP + i4 * 4] = v;
}

// ---------------- main router: 128 tok x 288 per CTA, legacy tf32 MMA ---------
__global__ void __launch_bounds__(TPB) router_kernel(
    const float* __restrict__ hs, float* __restrict__ out)
{
    extern __shared__ char smem[];
    const int tid = threadIdx.x;
    const int lane = tid & 31, wid = tid >> 5;
    const int rg = wid >> 2, cg = wid & 3;       // 4x4 warp grid: 32 rows x 72 cols
    const int token0 = blockIdx.x * 128;
    const u32 smb = (u32)__cvta_generic_to_shared(smem) + 1024;
    int* sbg = (int*)smem;                       // 128 ints in header

    // ---- chunk loader (A raw fp32: HW tf32 ignores low mantissa bits) ----
    const int arow = tid >> 2, aq2 = (tid & 3) * 2;
    auto load_chunk = [&](int c, int buf) {
        u32 ab = smb + buf * BUF_BYTES;
        u32 wb = ab + A_BYTES;
        const char* s = (const char*)(hs + (size_t)(token0 + arow) * HD + c * KCH) + aq2 * 16;
        cpa16(ab + arow * (AP * 4) + aq2 * 16, s);
        cpa16(ab + arow * (AP * 4) + aq2 * 16 + 16, s + 16);
        const char* wsrc = (const char*)g_wsw + (size_t)c * W_BYTES;
#pragma unroll
        for (int i = 0; i < 5; i++) {
            int idx = tid + i * TPB;
            if (idx < W_BYTES / 16) cpa16(wb + idx * 16, wsrc + (size_t)idx * 16);
        }
    };

    float acc[2][9][4];
#pragma unroll
    for (int m = 0; m < 2; m++)
#pragma unroll
        for (int t = 0; t < 9; t++)
#pragma unroll
            for (int i = 0; i < 4; i++) acc[m][t][i] = 0.f;

    load_chunk(0, 0);
    CP_COMMIT();

    const int r0 = rg * 32 + (lane >> 2);
    for (int c = 0; c < NCHUNK; c++) {
        const int b = c & 1;
        if (c + 1 < NCHUNK) { load_chunk(c + 1, b ^ 1); CP_COMMIT(); CP_WAIT1(); }
        else CP_WAIT0();
        __syncthreads();

        const float* A = (const float*)(smem + 1024) + b * (BUF_BYTES / 4);
        const float* wp = A + A_BYTES / 4 + (size_t)(cg * 32 + lane) * LP;

#pragma unroll
        for (int h = 0; h < 2; h++) {
            u32 a[2][2][4];
#pragma unroll
            for (int mt = 0; mt < 2; mt++)
#pragma unroll
                for (int kp = 0; kp < 2; kp++) {
                    int base = (r0 + mt * 16) * AP + (h * 2 + kp) * 8 + (lane & 3);
                    a[mt][kp][0] = __float_as_uint(A[base]);
                    a[mt][kp][1] = __float_as_uint(A[base + 8 * AP]);
                    a[mt][kp][2] = __float_as_uint(A[base + 4]);
                    a[mt][kp][3] = __float_as_uint(A[base + 8 * AP + 4]);
                }
#pragma unroll
            for (int t = 0; t < 9; t++) {
                float4 bv = *(const float4*)(wp + h * 36 + t * 4);
                u32 bx = __float_as_uint(bv.x), by = __float_as_uint(bv.y);
                u32 bz = __float_as_uint(bv.z), bw = __float_as_uint(bv.w);
                mma8(acc[0][t], a[0][0], bx, by);
                mma8(acc[0][t], a[0][1], bz, bw);
                mma8(acc[1][t], a[1][0], bx, by);
                mma8(acc[1][t], a[1][1], bz, bw);
            }
        }
        __syncthreads();
    }

    // ---- stage D to SMEM (overlay buffers) ----
    float* sC = (float*)(smem + 1024);
#pragma unroll
    for (int mt = 0; mt < 2; mt++) {
        int row = rg * 32 + mt * 16 + (lane >> 2);
        int colb = cg * 72 + 2 * (lane & 3);
#pragma unroll
        for (int t = 0; t < 9; t++) {
            int col = colb + t * 8;
            *(float2*)&sC[(size_t)row * SCSTR + col] =
                make_float2(acc[mt][t][0], acc[mt][t][1]);
            *(float2*)&sC[(size_t)(row + 8) * SCSTR + col] =
                make_float2(acc[mt][t][2], acc[mt][t][3]);
        }
    }
    __syncthreads();

    const size_t OSEL = (size_t)BT * EN;
    const size_t OWGT = OSEL + BT;

    // ---- per-token epilogue: group argmax, expert softmax/argmax, flag close calls
    if (tid < 128) {
        float* row = sC + (size_t)tid * SCSTR;
        float b1 = row[256], b2 = -1e30f; int bg = 0;
#pragma unroll
        for (int g = 1; g < GN; g++) {
            float v = row[256 + g];
            if (v > b1) { b2 = b1; b1 = v; bg = g; }
            else if (v > b2) b2 = v;
        }
        float m1 = row[bg * EPG], m2 = -1e30f; int bi = 0;
#pragma unroll
        for (int e = 1; e < EPG; e++) {
            float v = row[bg * EPG + e];
            if (v > m1) { m2 = m1; m1 = v; bi = e; }
            else if (v > m2) m2 = v;
        }
        float s = 0.f;
#pragma unroll
        for (int e = 0; e < EPG; e++) s += expf(row[bg * EPG + e] - m1);
        int token = token0 + tid;
        out[OSEL + token] = (float)(bg * EPG + bi);
        out[OWGT + token] = 1.0f / s;
        sbg[tid] = bg;
        if ((b1 - b2 < THR) || (m1 - m2 < THR)) {
            int sl = atomicAdd(&g_nfix, 1);
            g_fix[sl] = token;
        }
    }
    __syncthreads();

    // ---- cooperative [token, 256] logits row write (zeros outside selected block)
    const int slot0 = tid >> 6, th = tid & 63;
#pragma unroll 4
    for (int p = 0; p < 16; p++) {
        int slot = p * 8 + slot0;
        int bg = sbg[slot];
        float4 v = make_float4(0.f, 0.f, 0.f, 0.f);
        if ((th >> 2) == bg) {
            const float* row = sC + (size_t)slot * SCSTR + bg * EPG + (th & 3) * 4;
            v = make_float4(row[0], row[1], row[2], row[3]);
        }
        *(float4*)&out[(size_t)(token0 + slot) * EN + th * 4] = v;
    }
}

// ---------------- exact fp32 fixup for flagged tokens --------------------------
__global__ void fixup_kernel(const float* __restrict__ hs,
                             const float* __restrict__ gw,
                             const float* __restrict__ ew,
                             float* __restrict__ out)
{
    __shared__ float sg[GN], se[EPG];
    __shared__ int sbg_s;
    const int tid = threadIdx.x;
    const int wid = tid >> 5, lane = tid & 31;
    const size_t OSEL = (size_t)BT * EN, OWGT = OSEL + BT;
    const int n = g_nfix;

    for (int i = blockIdx.x; i < n; i += gridDim.x) {
        const int token = g_fix[i];
        const float4* x = (const float4*)(hs + (size_t)token * HD);
#pragma unroll
        for (int gg = 2 * wid; gg < 2 * wid + 2; gg++) {
            const float4* w = (const float4*)(gw + (size_t)gg * HD);
            float s = 0.f;
            for (int j = lane; j < HD / 4; j += 32) {
                float4 a = x[j], b = w[j];
                s += a.x * b.x + a.y * b.y + a.z * b.z + a.w * b.w;
            }
#pragma unroll
            for (int o = 16; o; o >>= 1) s += __shfl_xor_sync(0xFFFFFFFF, s, o);
            if (lane == 0) sg[gg] = s;
        }
        __syncthreads();
        if (tid == 0) {
            float best = sg[0]; int bg = 0;
#pragma unroll
            for (int g = 1; g < GN; g++) if (sg[g] > best) { best = sg[g]; bg = g; }
            sbg_s = bg;
        }
        __syncthreads();
        const int bg = sbg_s;
#pragma unroll
        for (int ee = 2 * wid; ee < 2 * wid + 2; ee++) {
            const float4* w = (const float4*)(ew + (size_t)(bg * EPG + ee) * HD);
            float s = 0.f;
            for (int j = lane; j < HD / 4; j += 32) {
                float4 a = x[j], b = w[j];
                s += a.x * b.x + a.y * b.y + a.z * b.z + a.w * b.w;
            }
#pragma unroll
            for (int o = 16; o; o >>= 1) s += __shfl_xor_sync(0xFFFFFFFF, s, o);
            if (lane == 0) se[ee] = s;
        }
        __syncthreads();
        if (tid == 0) {
            float m = se[0]; int bi = 0;
#pragma unroll
            for (int e = 1; e < EPG; e++) if (se[e] > m) { m = se[e]; bi = e; }
            float s = 0.f;
#pragma unroll
            for (int e = 0; e < EPG; e++) s += expf(se[e] - m);
            out[OSEL + token] = (float)(bg * EPG + bi);
            out[OWGT + token] = 1.0f / s;
        }
        if (tid < 64) {
            float4 v = make_float4(0.f, 0.f, 0.f, 0.f);
            if ((tid >> 2) == bg) {
                int lo = (tid & 3) * 4;
                v = make_float4(se[lo], se[lo + 1], se[lo + 2], se[lo + 3]);
            }
            *(float4*)&out[(size_t)token * EN + tid * 4] = v;
        }
        __syncthreads();
    }
}

extern "C" void kernel_launch(void* const* d_in, const int* in_sizes, int n_in,
                              void* d_out, int out_size) {
    const float* hs = (const float*)d_in[0];   // [32768, 4096]
    const float* gw = (const float*)d_in[1];   // [16, 4096]
    const float* ew = (const float*)d_in[2];   // [16, 16, 4096]
    float* out = (float*)d_out;

    cudaFuncSetAttribute(router_kernel,
                         cudaFuncAttributeMaxDynamicSharedMemorySize, SMEM_TOTAL);
    prep_kernel<<<1216, 256>>>(gw, ew);
    router_kernel<<<BT / 128, TPB, SMEM_TOTAL>>>(hs, out);
    fixup_kernel<<<64, 256>>>(hs, gw, ew, out);
}

// round 5
// speedup vs baseline: 1.6706x; 1.2787x over previous
#include <cuda_runtime.h>
#include <math.h>

typedef unsigned int u32;

#define BT 32768
#define HD 4096
#define GN 16
#define EPG 16
#define EN 256
#define KCH 32              // fp32 per K chunk (128 B per row)
#define NCHUNK 128          // 4096 / 32
#define TPB 256
#define THR 4e-3f

#define AW 36               // padded row stride in words (conflict-free frags)
#define A_WORDS (128 * AW)  // 4608
#define W_WORDS (16 * AW)   // 576
#define BUFW (A_WORDS + W_WORDS)   // 5184 words = 20736 B

__device__ __align__(16) float g_wr[272 * HD];   // tf32-RN weights: rows 0-255 expert, 256-271 group
__device__ int g_cnt[GN];
__device__ int g_bucket[GN][BT];
__device__ int g_nfix;
__device__ int g_fix[BT];

// ---------------- primitives (sm_80-era, safe on generic compute_103) ----------
__device__ __forceinline__ void cpa16(u32 dst, const void* src) {
    asm volatile("cp.async.cg.shared.global [%0], [%1], 16;\n" :: "r"(dst), "l"(src));
}
#define CP_COMMIT() asm volatile("cp.async.commit_group;\n" ::: "memory")
#define CP_WAIT1()  asm volatile("cp.async.wait_group 1;\n" ::: "memory")
#define CP_WAIT0()  asm volatile("cp.async.wait_group 0;\n" ::: "memory")

__device__ __forceinline__ void mma8(float* c, const u32* a, u32 b0, u32 b1) {
    asm volatile(
        "mma.sync.aligned.m16n8k8.row.col.f32.tf32.tf32.f32 "
        "{%0,%1,%2,%3}, {%4,%5,%6,%7}, {%8,%9}, {%0,%1,%2,%3};"
        : "+f"(c[0]), "+f"(c[1]), "+f"(c[2]), "+f"(c[3])
        : "r"(a[0]), "r"(a[1]), "r"(a[2]), "r"(a[3]), "r"(b0), "r"(b1));
}
__device__ __forceinline__ u32 tf32rn(float v) {
    u32 r; asm("cvt.rna.tf32.f32 %0, %1;" : "=r"(r) : "f"(v)); return r;
}
__device__ __forceinline__ u32 fb(float v) { return __float_as_uint(v); }

// ---------------- prep: round W to tf32-RN into one [272][4096] image ----------
__global__ void prep_kernel(const float* __restrict__ gw, const float* __restrict__ ew) {
    u32 u = blockIdx.x * 256 + threadIdx.x;     // 278528 = 272 * 1024 quads
    if (u < GN) g_cnt[u] = 0;
    if (u == GN) g_nfix = 0;
    u32 row = u >> 10, q = (u & 1023) * 4;
    const float* src = (row < 256) ? ew + (size_t)row * HD + q
                                   : gw + (size_t)(row - 256) * HD + q;
    float4 v = *(const float4*)src;
    float4 o;
    o.x = __uint_as_float(tf32rn(v.x)); o.y = __uint_as_float(tf32rn(v.y));
    o.z = __uint_as_float(tf32rn(v.z)); o.w = __uint_as_float(tf32rn(v.w));
    *(float4*)&g_wr[(size_t)row * HD + q] = o;
}

// ---------------- shared MMA tile body: D[128 x 16] += A[128 x 32] W^T ----------
// (A rows padded to AW words; W rows 0..15 padded to AW words, starting at A_WORDS)

// ---------------- phase 1: group logits, argmax, bucketing ---------------------
__global__ void __launch_bounds__(TPB) phase1_kernel(const float* __restrict__ hs)
{
    __shared__ float sbuf[2][BUFW];
    __shared__ int scnt[GN], sbase[GN], sbg[128], sloff[128];

    const int tid = threadIdx.x;
    const int lane = tid & 31, wid = tid >> 5;
    const int lx = lane & 3, ly = lane >> 2;
    const int m0 = wid * 16;
    const int token0 = blockIdx.x * 128;
    const u32 smb = (u32)__cvta_generic_to_shared(&sbuf[0][0]);

    const int arow = tid >> 1, ahalf = tid & 1;
    auto load = [&](int c, int b) {
        const char* srcA = (const char*)(hs + (size_t)(token0 + arow) * HD + c * KCH) + ahalf * 64;
        u32 da = smb + (u32)b * (BUFW * 4) + arow * (AW * 4) + ahalf * 64;
#pragma unroll
        for (int i = 0; i < 4; i++) cpa16(da + i * 16, srcA + i * 16);
        if (tid < 128) {
            const char* srcW = (const char*)(g_wr + (size_t)(256 + (tid >> 3)) * HD + c * KCH)
                               + (tid & 7) * 16;
            cpa16(smb + (u32)b * (BUFW * 4) + A_WORDS * 4 + (tid >> 3) * (AW * 4) + (tid & 7) * 16,
                  srcW);
        }
    };

    float acc[2][4] = {{0.f,0.f,0.f,0.f},{0.f,0.f,0.f,0.f}};
    load(0, 0); CP_COMMIT();

    for (int c = 0; c < NCHUNK; c++) {
        const int b = c & 1;
        if (c + 1 < NCHUNK) { load(c + 1, b ^ 1); CP_COMMIT(); CP_WAIT1(); }
        else CP_WAIT0();
        __syncthreads();
        const float* A = sbuf[b];
        const float* W = A + A_WORDS;
#pragma unroll
        for (int kk = 0; kk < 4; kk++) {
            int ra = (m0 + ly) * AW + kk * 8 + lx;
            u32 a[4] = { fb(A[ra]), fb(A[ra + 8 * AW]), fb(A[ra + 4]), fb(A[ra + 8 * AW + 4]) };
            int rb = ly * AW + kk * 8 + lx;
            mma8(acc[0], a, fb(W[rb]), fb(W[rb + 4]));
            mma8(acc[1], a, fb(W[rb + 8 * AW]), fb(W[rb + 8 * AW + 4]));
        }
        __syncthreads();
    }

    // stage D -> sC[128][18]
    float* sC = sbuf[0];
    {
        int row = m0 + ly;
#pragma unroll
        for (int n = 0; n < 2; n++) {
            int col = n * 8 + 2 * lx;
            sC[row * 18 + col] = acc[n][0];       sC[row * 18 + col + 1] = acc[n][1];
            sC[(row + 8) * 18 + col] = acc[n][2]; sC[(row + 8) * 18 + col + 1] = acc[n][3];
        }
    }
    if (tid < GN) scnt[tid] = 0;
    __syncthreads();

    if (tid < 128) {
        const float* row = sC + tid * 18;
        float b1 = row[0], b2 = -1e30f; int bg = 0;
#pragma unroll
        for (int g = 1; g < GN; g++) {
            float v = row[g];
            if (v > b1) { b2 = b1; b1 = v; bg = g; }
            else if (v > b2) b2 = v;
        }
        sbg[tid] = bg;
        sloff[tid] = atomicAdd(&scnt[bg], 1);
        if (b1 - b2 < THR) g_fix[atomicAdd(&g_nfix, 1)] = token0 + tid;
    }
    __syncthreads();
    if (tid < GN) sbase[tid] = atomicAdd(&g_cnt[tid], scnt[tid]);
    __syncthreads();
    if (tid < 128) g_bucket[sbg[tid]][sbase[sbg[tid]] + sloff[tid]] = token0 + tid;
}

// ---------------- phase 2: per-group expert GEMM + epilogue --------------------
__global__ void __launch_bounds__(TPB) phase2_kernel(
    const float* __restrict__ hs, float* __restrict__ out)
{
    __shared__ float sbuf[2][BUFW];
    __shared__ int stok[128];

    const int tid = threadIdx.x;
    const int lane = tid & 31, wid = tid >> 5;
    const int lx = lane & 3, ly = lane >> 2;
    const int m0 = wid * 16;
    const int g = blockIdx.x;
    const int cnt = g_cnt[g];
    const u32 smb = (u32)__cvta_generic_to_shared(&sbuf[0][0]);
    const size_t OSEL = (size_t)BT * EN, OWGT = OSEL + BT;

    const int arow = tid >> 1, ahalf = tid & 1;
    auto load = [&](int c, int b) {
        int tok = stok[arow];
        if (tok >= 0) {
            const char* srcA = (const char*)(hs + (size_t)tok * HD + c * KCH) + ahalf * 64;
            u32 da = smb + (u32)b * (BUFW * 4) + arow * (AW * 4) + ahalf * 64;
#pragma unroll
            for (int i = 0; i < 4; i++) cpa16(da + i * 16, srcA + i * 16);
        }
        if (tid < 128) {
            const char* srcW = (const char*)(g_wr + (size_t)(g * EPG + (tid >> 3)) * HD + c * KCH)
                               + (tid & 7) * 16;
            cpa16(smb + (u32)b * (BUFW * 4) + A_WORDS * 4 + (tid >> 3) * (AW * 4) + (tid & 7) * 16,
                  srcW);
        }
    };

    for (int tile = blockIdx.y; tile * 128 < cnt; tile += gridDim.y) {
        __syncthreads();
        if (tid < 128) {
            int i = tile * 128 + tid;
            stok[tid] = (i < cnt) ? g_bucket[g][i] : -1;
        }
        __syncthreads();

        float acc[2][4] = {{0.f,0.f,0.f,0.f},{0.f,0.f,0.f,0.f}};
        load(0, 0); CP_COMMIT();

        for (int c = 0; c < NCHUNK; c++) {
            const int b = c & 1;
            if (c + 1 < NCHUNK) { load(c + 1, b ^ 1); CP_COMMIT(); CP_WAIT1(); }
            else CP_WAIT0();
            __syncthreads();
            const float* A = sbuf[b];
            const float* W = A + A_WORDS;
#pragma unroll
            for (int kk = 0; kk < 4; kk++) {
                int ra = (m0 + ly) * AW + kk * 8 + lx;
                u32 a[4] = { fb(A[ra]), fb(A[ra + 8 * AW]), fb(A[ra + 4]), fb(A[ra + 8 * AW + 4]) };
                int rb = ly * AW + kk * 8 + lx;
                mma8(acc[0], a, fb(W[rb]), fb(W[rb + 4]));
                mma8(acc[1], a, fb(W[rb + 8 * AW]), fb(W[rb + 8 * AW + 4]));
            }
            __syncthreads();
        }

        float* sC = sbuf[0];
        {
            int row = m0 + ly;
#pragma unroll
            for (int n = 0; n < 2; n++) {
                int col = n * 8 + 2 * lx;
                sC[row * 18 + col] = acc[n][0];       sC[row * 18 + col + 1] = acc[n][1];
                sC[(row + 8) * 18 + col] = acc[n][2]; sC[(row + 8) * 18 + col + 1] = acc[n][3];
            }
        }
        __syncthreads();

        if (tid < 128 && stok[tid] >= 0) {
            const float* row = sC + tid * 18;
            float m1 = row[0], m2 = -1e30f; int bi = 0;
#pragma unroll
            for (int e = 1; e < EPG; e++) {
                float v = row[e];
                if (v > m1) { m2 = m1; m1 = v; bi = e; }
                else if (v > m2) m2 = v;
            }
            float s = 0.f;
#pragma unroll
            for (int e = 0; e < EPG; e++) s += expf(row[e] - m1);
            int token = stok[tid];
            out[OSEL + token] = (float)(g * EPG + bi);
            out[OWGT + token] = 1.0f / s;
            if (m1 - m2 < THR) g_fix[atomicAdd(&g_nfix, 1)] = token;
        }
        __syncthreads();

        // cooperative full [token, 256] row write (zeros outside block g)
        const int slot0 = tid >> 6, th = tid & 63;
#pragma unroll 4
        for (int p = 0; p < 32; p++) {
            int slot = p * 4 + slot0;
            int token = stok[slot];
            if (token >= 0) {
                float4 v = make_float4(0.f, 0.f, 0.f, 0.f);
                if ((th >> 2) == g) {
                    const float* row = sC + slot * 18 + (th & 3) * 4;
                    v = make_float4(row[0], row[1], row[2], row[3]);
                }
                *(float4*)&out[(size_t)token * EN + th * 4] = v;
            }
        }
    }
}

// ---------------- exact fp32 fixup for flagged tokens --------------------------
__global__ void fixup_kernel(const float* __restrict__ hs,
                             const float* __restrict__ gw,
                             const float* __restrict__ ew,
                             float* __restrict__ out)
{
    __shared__ float sg[GN], se[EPG];
    __shared__ int sbg_s;
    const int tid = threadIdx.x;
    const int wid = tid >> 5, lane = tid & 31;
    const size_t OSEL = (size_t)BT * EN, OWGT = OSEL + BT;
    const int n = g_nfix;

    for (int i = blockIdx.x; i < n; i += gridDim.x) {
        const int token = g_fix[i];
        const float4* x = (const float4*)(hs + (size_t)token * HD);
#pragma unroll
        for (int gg = 2 * wid; gg < 2 * wid + 2; gg++) {
            const float4* w = (const float4*)(gw + (size_t)gg * HD);
            float s = 0.f;
            for (int j = lane; j < HD / 4; j += 32) {
                float4 a = x[j], b = w[j];
                s += a.x * b.x + a.y * b.y + a.z * b.z + a.w * b.w;
            }
#pragma unroll
            for (int o = 16; o; o >>= 1) s += __shfl_xor_sync(0xFFFFFFFF, s, o);
            if (lane == 0) sg[gg] = s;
        }
        __syncthreads();
        if (tid == 0) {
            float best = sg[0]; int bg = 0;
#pragma unroll
            for (int g = 1; g < GN; g++) if (sg[g] > best) { best = sg[g]; bg = g; }
            sbg_s = bg;
        }
        __syncthreads();
        const int bg = sbg_s;
#pragma unroll
        for (int ee = 2 * wid; ee < 2 * wid + 2; ee++) {
            const float4* w = (const float4*)(ew + (size_t)(bg * EPG + ee) * HD);
            float s = 0.f;
            for (int j = lane; j < HD / 4; j += 32) {
                float4 a = x[j], b = w[j];
                s += a.x * b.x + a.y * b.y + a.z * b.z + a.w * b.w;
            }
#pragma unroll
            for (int o = 16; o; o >>= 1) s += __shfl_xor_sync(0xFFFFFFFF, s, o);
            if (lane == 0) se[ee] = s;
        }
        __syncthreads();
        if (tid == 0) {
            float m = se[0]; int bi = 0;
#pragma unroll
            for (int e = 1; e < EPG; e++) if (se[e] > m) { m = se[e]; bi = e; }
            float s = 0.f;
#pragma unroll
            for (int e = 0; e < EPG; e++) s += expf(se[e] - m);
            out[OSEL + token] = (float)(bg * EPG + bi);
            out[OWGT + token] = 1.0f / s;
        }
        if (tid < 64) {
            float4 v = make_float4(0.f, 0.f, 0.f, 0.f);
            if ((tid >> 2) == bg) {
                int lo = (tid & 3) * 4;
                v = make_float4(se[lo], se[lo + 1], se[lo + 2], se[lo + 3]);
            }
            *(float4*)&out[(size_t)token * EN + tid * 4] = v;
        }
        __syncthreads();
    }
}

extern "C" void kernel_launch(void* const* d_in, const int* in_sizes, int n_in,
                              void* d_out, int out_size) {
    const float* hs = (const float*)d_in[0];   // [32768, 4096]
    const float* gw = (const float*)d_in[1];   // [16, 4096]
    const float* ew = (const float*)d_in[2];   // [16, 16, 4096]
    float* out = (float*)d_out;

    prep_kernel<<<1088, 256>>>(gw, ew);
    phase1_kernel<<<BT / 128, TPB>>>(hs);
    phase2_kernel<<<dim3(GN, 12), TPB>>>(hs, out);
    fixup_kernel<<<64, 256>>>(hs, gw, ew, out);
}

// round 6
// speedup vs baseline: 1.9837x; 1.1874x over previous
#include <cuda_runtime.h>
#include <math.h>

typedef unsigned int u32;

#define BT 32768
#define HD 4096
#define GN 16
#define EPG 16
#define EN 256
#define KCH 32              // fp32 per K chunk (128 B per token row)
#define NCHUNK 128          // 4096 / 32
#define TPB 256
#define TOKT 64             // tokens per CTA tile
#define THR 5e-5f

#define AW 36               // padded row stride (words) -> conflict-free frags
#define A_WORDS (TOKT * AW)         // 2304
#define WP_WORDS (16 * AW)          // 576 per plane
#define BUFW (A_WORDS + 2 * WP_WORDS)  // 3456 words = 13824 B
#define NSTG 4

__device__ __align__(16) float g_whi[272 * HD];  // rows 0-255 expert, 256-271 group
__device__ __align__(16) float g_wlo[272 * HD];
__device__ int g_cnt[GN];
__device__ int g_bucket[GN][BT];
__device__ int g_nfix;
__device__ int g_fix[BT];

// ---------------- primitives (sm_80-era, safe on generic compute_103) ----------
__device__ __forceinline__ void cpa16(u32 dst, const void* src) {
    asm volatile("cp.async.cg.shared.global [%0], [%1], 16;\n" :: "r"(dst), "l"(src));
}
#define CP_COMMIT() asm volatile("cp.async.commit_group;\n" ::: "memory")
#define CP_WAIT3()  asm volatile("cp.async.wait_group 3;\n" ::: "memory")

__device__ __forceinline__ void mma8(float* c, const u32* a, u32 b0, u32 b1) {
    asm volatile(
        "mma.sync.aligned.m16n8k8.row.col.f32.tf32.tf32.f32 "
        "{%0,%1,%2,%3}, {%4,%5,%6,%7}, {%8,%9}, {%0,%1,%2,%3};"
        : "+f"(c[0]), "+f"(c[1]), "+f"(c[2]), "+f"(c[3])
        : "r"(a[0]), "r"(a[1]), "r"(a[2]), "r"(a[3]), "r"(b0), "r"(b1));
}
__device__ __forceinline__ u32 tf32rn(float v) {
    u32 r; asm("cvt.rna.tf32.f32 %0, %1;" : "=r"(r) : "f"(v)); return r;
}
__device__ __forceinline__ u32 fb(float v) { return __float_as_uint(v); }

// ---------------- prep: W -> (hi = tf32rn(w), lo = w - hi) planes --------------
__global__ void prep_kernel(const float* __restrict__ gw, const float* __restrict__ ew) {
    u32 u = blockIdx.x * 256 + threadIdx.x;     // 278528 = 272 * 1024 quads
    if (u < GN) g_cnt[u] = 0;
    if (u == GN) g_nfix = 0;
    u32 row = u >> 10, q = (u & 1023) * 4;
    const float* src = (row < 256) ? ew + (size_t)row * HD + q
                                   : gw + (size_t)(row - 256) * HD + q;
    float4 v = *(const float4*)src;
    float4 h, l;
    h.x = __uint_as_float(tf32rn(v.x)); l.x = v.x - h.x;
    h.y = __uint_as_float(tf32rn(v.y)); l.y = v.y - h.y;
    h.z = __uint_as_float(tf32rn(v.z)); l.z = v.z - h.z;
    h.w = __uint_as_float(tf32rn(v.w)); l.w = v.w - h.w;
    *(float4*)&g_whi[(size_t)row * HD + q] = h;
    *(float4*)&g_wlo[(size_t)row * HD + q] = l;
}

// ---------------- MMA tile core (shared by both phases) ------------------------
// D[64 x 16] = A[64 x 4096] * W[16 x 4096]^T, 3-mma tf32 split, 4-stage pipeline.
// wrow0: W row offset in g_whi/g_wlo. Token row r loads hs row tokof(r).
struct P1Tok { int t0; __device__ int operator()(int r) const { return t0 + r; } };
struct P2Tok { const int* s; __device__ int operator()(int r) const { return s[r]; } };

template <typename TOKF>
__device__ __forceinline__ void mma_tile(
    const float* __restrict__ hs, int wrow0, TOKF tokof,
    float (&sbuf)[NSTG][BUFW], float* acc /* [4] */)
{
    const int tid = threadIdx.x;
    const int lane = tid & 31;
    const int wid = tid >> 5;
    const int lx = lane & 3, ly = lane >> 2;
    const int m0 = (wid >> 1) * 16;
    const int nb = (wid & 1) * 8;
    const u32 smb = (u32)__cvta_generic_to_shared(&sbuf[0][0]);

    const int arow = tid >> 2, aq = tid & 3;         // 64 rows x 32B quarters
    const int wplane = tid >> 7, wi = tid & 127;     // 2 planes x 128 16B-units
    const int wrow = wi >> 3, wu = wi & 7;
    const float* wsrc_base = (wplane ? g_wlo : g_whi) + (size_t)(wrow0 + wrow) * HD + wu * 4;

    acc[0] = acc[1] = acc[2] = acc[3] = 0.f;

    auto load = [&](int c) {
        const int b = c & (NSTG - 1);
        u32 base = smb + (u32)b * (BUFW * 4);
        int tok = tokof(arow);
        if (tok >= 0) {
            const char* sA = (const char*)(hs + (size_t)tok * HD + c * KCH) + aq * 32;
            u32 da = base + arow * (AW * 4) + aq * 32;
            cpa16(da, sA);
            cpa16(da + 16, sA + 16);
        }
        cpa16(base + A_WORDS * 4 + wplane * (WP_WORDS * 4) + wrow * (AW * 4) + wu * 16,
              (const char*)(wsrc_base + (size_t)c * KCH));
    };

    load(0); CP_COMMIT();
    load(1); CP_COMMIT();
    load(2); CP_COMMIT();

    for (int c = 0; c < NCHUNK; c++) {
        if (c + 3 < NCHUNK) load(c + 3);
        CP_COMMIT();
        CP_WAIT3();
        __syncthreads();
        const float* A = sbuf[c & (NSTG - 1)];
        const float* Wh = A + A_WORDS;
        const float* Wl = Wh + WP_WORDS;
#pragma unroll
        for (int kk = 0; kk < 4; kk++) {
            int ra = (m0 + ly) * AW + kk * 8 + lx;
            float a0 = A[ra], a1 = A[ra + 8 * AW], a2 = A[ra + 4], a3 = A[ra + 8 * AW + 4];
            u32 ahi[4] = { tf32rn(a0), tf32rn(a1), tf32rn(a2), tf32rn(a3) };
            u32 alo[4] = { fb(a0 - __uint_as_float(ahi[0])),
                           fb(a1 - __uint_as_float(ahi[1])),
                           fb(a2 - __uint_as_float(ahi[2])),
                           fb(a3 - __uint_as_float(ahi[3])) };
            int rb = (nb + ly) * AW + kk * 8 + lx;
            u32 bh0 = fb(Wh[rb]), bh1 = fb(Wh[rb + 4]);
            u32 bl0 = fb(Wl[rb]), bl1 = fb(Wl[rb + 4]);
            mma8(acc, ahi, bh0, bh1);
            mma8(acc, alo, bh0, bh1);
            mma8(acc, ahi, bl0, bl1);
        }
        __syncthreads();
    }
}

// stage acc -> sC[64][18]
__device__ __forceinline__ void stage_c(float* sC, const float* acc) {
    const int tid = threadIdx.x;
    const int lane = tid & 31, wid = tid >> 5;
    const int lx = lane & 3, ly = lane >> 2;
    const int m0 = (wid >> 1) * 16, nb = (wid & 1) * 8;
    int row = m0 + ly, col = nb + 2 * lx;
    sC[row * 18 + col] = acc[0];       sC[row * 18 + col + 1] = acc[1];
    sC[(row + 8) * 18 + col] = acc[2]; sC[(row + 8) * 18 + col + 1] = acc[3];
}

// ---------------- phase 1: group logits, argmax, bucketing ---------------------
__global__ void __launch_bounds__(TPB) phase1_kernel(const float* __restrict__ hs)
{
    __shared__ float sbuf[NSTG][BUFW];
    __shared__ int scnt[GN], sbase[GN], sbg[TOKT], sloff[TOKT];

    const int tid = threadIdx.x;
    const int token0 = blockIdx.x * TOKT;

    float acc[4];
    mma_tile(hs, 256, P1Tok{token0}, sbuf, acc);

    float* sC = &sbuf[0][0];
    stage_c(sC, acc);
    if (tid < GN) scnt[tid] = 0;
    __syncthreads();

    if (tid < TOKT) {
        const float* row = sC + tid * 18;
        float b1 = row[0], b2 = -1e30f; int bg = 0;
#pragma unroll
        for (int g = 1; g < GN; g++) {
            float v = row[g];
            if (v > b1) { b2 = b1; b1 = v; bg = g; }
            else if (v > b2) b2 = v;
        }
        sbg[tid] = bg;
        sloff[tid] = atomicAdd(&scnt[bg], 1);
        if (b1 - b2 < THR) g_fix[atomicAdd(&g_nfix, 1)] = token0 + tid;
    }
    __syncthreads();
    if (tid < GN) sbase[tid] = atomicAdd(&g_cnt[tid], scnt[tid]);
    __syncthreads();
    if (tid < TOKT) g_bucket[sbg[tid]][sbase[sbg[tid]] + sloff[tid]] = token0 + tid;
}

// ---------------- phase 2: per-group expert GEMM + epilogue --------------------
__global__ void __launch_bounds__(TPB) phase2_kernel(
    const float* __restrict__ hs, float* __restrict__ out)
{
    __shared__ float sbuf[NSTG][BUFW];
    __shared__ int stok[TOKT];

    const int tid = threadIdx.x;
    const int g = blockIdx.x;
    const int cnt = g_cnt[g];
    const size_t OSEL = (size_t)BT * EN, OWGT = OSEL + BT;

    for (int tile = blockIdx.y; tile * TOKT < cnt; tile += gridDim.y) {
        __syncthreads();
        if (tid < TOKT) {
            int i = tile * TOKT + tid;
            stok[tid] = (i < cnt) ? g_bucket[g][i] : -1;
        }
        __syncthreads();

        float acc[4];
        mma_tile(hs, g * EPG, P2Tok{stok}, sbuf, acc);

        float* sC = &sbuf[0][0];
        stage_c(sC, acc);
        __syncthreads();

        if (tid < TOKT && stok[tid] >= 0) {
            const float* row = sC + tid * 18;
            float m1 = row[0], m2 = -1e30f; int bi = 0;
#pragma unroll
            for (int e = 1; e < EPG; e++) {
                float v = row[e];
                if (v > m1) { m2 = m1; m1 = v; bi = e; }
                else if (v > m2) m2 = v;
            }
            float s = 0.f;
#pragma unroll
            for (int e = 0; e < EPG; e++) s += expf(row[e] - m1);
            int token = stok[tid];
            out[OSEL + token] = (float)(g * EPG + bi);
            out[OWGT + token] = 1.0f / s;
            if (m1 - m2 < THR) g_fix[atomicAdd(&g_nfix, 1)] = token;
        }
        __syncthreads();

        // cooperative full [token, 256] row write (zeros outside block g)
        const int slot0 = tid >> 6, th = tid & 63;
#pragma unroll 4
        for (int p = 0; p < 16; p++) {
            int slot = p * 4 + slot0;
            int token = stok[slot];
            if (token >= 0) {
                float4 v = make_float4(0.f, 0.f, 0.f, 0.f);
                if ((th >> 2) == g) {
                    const float* row = sC + slot * 18 + (th & 3) * 4;
                    v = make_float4(row[0], row[1], row[2], row[3]);
                }
                *(float4*)&out[(size_t)token * EN + th * 4] = v;
            }
        }
    }
}

// ---------------- exact fp32 fixup for flagged tokens --------------------------
__global__ void fixup_kernel(const float* __restrict__ hs,
                             const float* __restrict__ gw,
                             const float* __restrict__ ew,
                             float* __restrict__ out)
{
    __shared__ float sg[GN], se[EPG];
    __shared__ int sbg_s;
    const int tid = threadIdx.x;
    const int wid = tid >> 5, lane = tid & 31;
    const size_t OSEL = (size_t)BT * EN, OWGT = OSEL + BT;
    const int n = g_nfix;

    for (int i = blockIdx.x; i < n; i += gridDim.x) {
        const int token = g_fix[i];
        const float4* x = (const float4*)(hs + (size_t)token * HD);
#pragma unroll
        for (int gg = 2 * wid; gg < 2 * wid + 2; gg++) {
            const float4* w = (const float4*)(gw + (size_t)gg * HD);
            float s = 0.f;
            for (int j = lane; j < HD / 4; j += 32) {
                float4 a = x[j], b = w[j];
                s += a.x * b.x + a.y * b.y + a.z * b.z + a.w * b.w;
            }
#pragma unroll
            for (int o = 16; o; o >>= 1) s += __shfl_xor_sync(0xFFFFFFFF, s, o);
            if (lane == 0) sg[gg] = s;
        }
        __syncthreads();
        if (tid == 0) {
            float best = sg[0]; int bg = 0;
#pragma unroll
            for (int g = 1; g < GN; g++) if (sg[g] > best) { best = sg[g]; bg = g; }
            sbg_s = bg;
        }
        __syncthreads();
        const int bg = sbg_s;
#pragma unroll
        for (int ee = 2 * wid; ee < 2 * wid + 2; ee++) {
            const float4* w = (const float4*)(ew + (size_t)(bg * EPG + ee) * HD);
            float s = 0.f;
            for (int j = lane; j < HD / 4; j += 32) {
                float4 a = x[j], b = w[j];
                s += a.x * b.x + a.y * b.y + a.z * b.z + a.w * b.w;
            }
#pragma unroll
            for (int o = 16; o; o >>= 1) s += __shfl_xor_sync(0xFFFFFFFF, s, o);
            if (lane == 0) se[ee] = s;
        }
        __syncthreads();
        if (tid == 0) {
            float m = se[0]; int bi = 0;
#pragma unroll
            for (int e = 1; e < EPG; e++) if (se[e] > m) { m = se[e]; bi = e; }
            float s = 0.f;
#pragma unroll
            for (int e = 0; e < EPG; e++) s += expf(se[e] - m);
            out[OSEL + token] = (float)(bg * EPG + bi);
            out[OWGT + token] = 1.0f / s;
        }
        if (tid < 64) {
            float4 v = make_float4(0.f, 0.f, 0.f, 0.f);
            if ((tid >> 2) == bg) {
                int lo = (tid & 3) * 4;
                v = make_float4(se[lo], se[lo + 1], se[lo + 2], se[lo + 3]);
            }
            *(float4*)&out[(size_t)token * EN + tid * 4] = v;
        }
        __syncthreads();
    }
}

extern "C" void kernel_launch(void* const* d_in, const int* in_sizes, int n_in,
                              void* d_out, int out_size) {
    const float* hs = (const float*)d_in[0];   // [32768, 4096]
    const float* gw = (const float*)d_in[1];   // [16, 4096]
    const float* ew = (const float*)d_in[2];   // [16, 16, 4096]
    float* out = (float*)d_out;

    prep_kernel<<<1088, 256>>>(gw, ew);
    phase1_kernel<<<BT / TOKT, TPB>>>(hs);
    phase2_kernel<<<dim3(GN, 32), TPB>>>(hs, out);
    fixup_kernel<<<64, 256>>>(hs, gw, ew, out);
}